// round 15
// baseline (speedup 1.0000x reference)
#include <cuda_runtime.h>
#include <cuda_fp16.h>
#include <math.h>
#include <stdint.h>

#define BB 8
#define NN 8192
#define SS 2048
#define C1 128
#define C2 256
#define CIN 384
#define H1 256
#define H2 128
#define M_TOTAL (BB * NN)   /* 65536 */
#define BN_EPS 1e-5f
#define QPB 64              /* queries per KNN block (8 threads each, 512-thread block) */

// ================= scratch (static device globals; no allocation) =================
__device__ __align__(16) __half g_yh[(size_t)M_TOTAL * H1];    // 32 MB GEMM1 out fp16 (pre-BN)
__device__ float g_sum1[H1];
__device__ float g_sumsq1[H1];
__device__ float g_sum2[H2];
__device__ float g_sumsq2[H2];
// activations fp16
__device__ __align__(16) __half g_A1[(size_t)M_TOTAL * CIN];   // 48 MB
// weights fp16 [n][k]
__device__ __align__(16) __half g_W1f[H1 * CIN];
__device__ __align__(16) __half g_W2f[H2 * H1];

// ================= helpers =================
__device__ __forceinline__ uint32_t smem_u32(const void* p) {
    uint32_t a;
    asm("{ .reg .u64 t; cvta.to.shared.u64 t, %1; cvt.u32.u64 %0, t; }" : "=r"(a) : "l"(p));
    return a;
}
__device__ __forceinline__ void ldsm4(uint32_t* r, uint32_t addr) {
    asm volatile("ldmatrix.sync.aligned.m8n8.x4.shared.b16 {%0,%1,%2,%3}, [%4];"
        : "=r"(r[0]), "=r"(r[1]), "=r"(r[2]), "=r"(r[3]) : "r"(addr));
}
__device__ __forceinline__ void ldsm2(uint32_t* r, uint32_t addr) {
    asm volatile("ldmatrix.sync.aligned.m8n8.x2.shared.b16 {%0,%1}, [%2];"
        : "=r"(r[0]), "=r"(r[1]) : "r"(addr));
}
__device__ __forceinline__ void mma_f16(float* c, const uint32_t* a, const uint32_t* b) {
    asm volatile(
        "mma.sync.aligned.m16n8k16.row.col.f32.f16.f16.f32 "
        "{%0,%1,%2,%3}, {%4,%5,%6,%7}, {%8,%9}, {%0,%1,%2,%3};\n"
        : "+f"(c[0]), "+f"(c[1]), "+f"(c[2]), "+f"(c[3])
        : "r"(a[0]), "r"(a[1]), "r"(a[2]), "r"(a[3]), "r"(b[0]), "r"(b[1]));
}
__device__ __forceinline__ void cp16(uint32_t dst, const void* src) {
    asm volatile("cp.async.cg.shared.global [%0], [%1], 16;" :: "r"(dst), "l"(src));
}
#define CP_COMMIT() asm volatile("cp.async.commit_group;" ::: "memory")
#define CP_WAIT1()  asm volatile("cp.async.wait_group 1;" ::: "memory")

// ================= kernel: weight prep + stats zero (fused) =================
__global__ __launch_bounds__(256) void prep_weights_kernel(
    const float* __restrict__ W1, const float* __restrict__ W2)
{
    int i = blockIdx.x * blockDim.x + threadIdx.x;
    if (blockIdx.x == 0) {
        int t = threadIdx.x;
        if (t < H1) { g_sum1[t] = 0.f; g_sumsq1[t] = 0.f; }
        if (t < H2) { g_sum2[t] = 0.f; g_sumsq2[t] = 0.f; }
    }
    if (i < H1 * CIN) {
        g_W1f[i] = __float2half_rn(W1[i]);
    } else {
        int j = i - H1 * CIN;
        if (j < H2 * H1) g_W2f[j] = __float2half_rn(W2[j]);
    }
}

// ================= kernel: 3-NN (8 thr/query, interleaved) + interp + feat1 convert =================
__global__ __launch_bounds__(512) void knn_interp_kernel(
    const float* __restrict__ xyz1,
    const float* __restrict__ xyz2,
    const float* __restrict__ feat2,
    const float* __restrict__ feat1)
{
    __shared__ float4 s_p[SS];          // 32 KB
    __shared__ float  s_w[QPB][3];
    __shared__ int    s_i[QPB][3];

    const int b   = blockIdx.y;
    const int n0  = blockIdx.x * QPB;
    const int tid = threadIdx.x;
    const int qid = tid >> 3;
    const int sub = tid & 7;

    const float* p2 = xyz2 + (size_t)b * SS * 3;
    for (int j = tid; j < SS; j += 512) {
        float x = p2[j * 3 + 0];
        float y = p2[j * 3 + 1];
        float z = p2[j * 3 + 2];
        s_p[j] = make_float4(x, y, z, x * x + y * y + z * z);
    }
    __syncthreads();

    const int   n  = n0 + qid;
    const float* q = xyz1 + ((size_t)b * NN + n) * 3;
    const float qx = q[0], qy = q[1], qz = q[2];
    const float n1 = qx * qx + qy * qy + qz * qz;
    const float mx = -2.f * qx, my = -2.f * qy, mz = -2.f * qz;

    float d0 = 1e30f, d1 = 1e30f, d2v = 1e30f;
    int   i0 = 0, i1 = 0, i2 = 0;

#pragma unroll 8
    for (int jj = 0; jj < SS / 8; jj++) {
        const int j = (jj << 3) | sub;
        float4 c = s_p[j];
        float s = fmaf(mx, c.x, fmaf(my, c.y, fmaf(mz, c.z, c.w)));
        if (s < d2v) {
            if (s < d1) {
                d2v = d1; i2 = i1;
                if (s < d0) { d1 = d0; i1 = i0; d0 = s; i0 = j; }
                else        { d1 = s;  i1 = j; }
            } else {
                d2v = s; i2 = j;
            }
        }
    }

#pragma unroll
    for (int m = 1; m <= 4; m <<= 1) {
        float e0 = __shfl_xor_sync(0xffffffffu, d0, m);
        float e1 = __shfl_xor_sync(0xffffffffu, d1, m);
        float e2 = __shfl_xor_sync(0xffffffffu, d2v, m);
        int   f0 = __shfl_xor_sync(0xffffffffu, i0, m);
        int   f1 = __shfl_xor_sync(0xffffffffu, i1, m);
        int   f2 = __shfl_xor_sync(0xffffffffu, i2, m);
        float es[3] = {e0, e1, e2};
        int   fs[3] = {f0, f1, f2};
#pragma unroll
        for (int t = 0; t < 3; t++) {
            float s = es[t]; int j = fs[t];
            if (s < d2v) {
                if (s < d1) {
                    d2v = d1; i2 = i1;
                    if (s < d0) { d1 = d0; i1 = i0; d0 = s; i0 = j; }
                    else        { d1 = s;  i1 = j; }
                } else {
                    d2v = s; i2 = j;
                }
            }
        }
    }

    if (sub == 0) {
        float da = sqrtf(fmaxf(n1 + d0, 0.f)) + 1e-10f;
        float db = sqrtf(fmaxf(n1 + d1, 0.f)) + 1e-10f;
        float dc = sqrtf(fmaxf(n1 + d2v, 0.f)) + 1e-10f;
        float w0 = 1.f / da, w1 = 1.f / db, w2 = 1.f / dc;
        float inv = 1.f / (w0 + w1 + w2);
        s_w[qid][0] = w0 * inv; s_w[qid][1] = w1 * inv; s_w[qid][2] = w2 * inv;
        s_i[qid][0] = i0; s_i[qid][1] = i1; s_i[qid][2] = i2;
    }
    __syncthreads();

    const int lane = tid & 31;
    const int warp = tid >> 5;
    const float4* f2b = (const float4*)(feat2 + (size_t)b * SS * C2);
    for (int pl = warp; pl < QPB; pl += 16) {
        const float a0 = s_w[pl][0], a1 = s_w[pl][1], a2 = s_w[pl][2];
        const float4* r0 = f2b + (size_t)s_i[pl][0] * (C2 / 4);
        const float4* r1 = f2b + (size_t)s_i[pl][1] * (C2 / 4);
        const float4* r2 = f2b + (size_t)s_i[pl][2] * (C2 / 4);
        const size_t rowo = (size_t)(b * NN + n0 + pl) * CIN;
#pragma unroll
        for (int c = lane; c < C2 / 4; c += 32) {
            float4 va = r0[c], vb = r1[c], vc = r2[c];
            float o0 = a0 * va.x + a1 * vb.x + a2 * vc.x;
            float o1 = a0 * va.y + a1 * vb.y + a2 * vc.y;
            float o2 = a0 * va.z + a1 * vb.z + a2 * vc.z;
            float o3 = a0 * va.w + a1 * vb.w + a2 * vc.w;
            union { uint2 u; __half h[4]; } pk;
            pk.h[0] = __float2half_rn(o0);
            pk.h[1] = __float2half_rn(o1);
            pk.h[2] = __float2half_rn(o2);
            pk.h[3] = __float2half_rn(o3);
            *(uint2*)(g_A1 + rowo + c * 4) = pk.u;
        }
    }

    for (int t = tid; t < QPB * (C1 / 4); t += 512) {
        const int r  = t >> 5;
        const int c4 = (t & 31) * 4;
        const size_t row = (size_t)b * NN + n0 + r;
        float4 v = *(const float4*)(feat1 + row * C1 + c4);
        union { uint2 u; __half h[4]; } pk;
        pk.h[0] = __float2half_rn(v.x);
        pk.h[1] = __float2half_rn(v.y);
        pk.h[2] = __float2half_rn(v.z);
        pk.h[3] = __float2half_rn(v.w);
        *(uint2*)(g_A1 + row * CIN + C2 + c4) = pk.u;
    }
}

// ================= fp16 cp.async MMA GEMM, M64 tiles, K64 stages =================
// Block 256 thr / 8 warps; tile 64(M) x 128(N) x 64(K); warp tile 32x32.
// 3-stage ring, 24KB/stage: A 8KB (64 rows x 128B) | B 16KB (128 rows x 128B).
// Row = 128B = 8 chunks of 16B; chunk c stored at c ^ (r & 7) (conflict-free ldmatrix).
// GEMM2 fuses BN1+ReLU into A fragments after ldmatrix (raw g_yh in smem).
#define A_STAGE    8192
#define GEMM_STAGE 24576
#define GEMM_SMEM  (3 * GEMM_STAGE)

template<int GEMM>   // 1: A1 x W1 -> g_yh ; 2: relu(bn1(g_yh)) x W2 -> out
__global__ void __launch_bounds__(256) gemm_mma_kernel(
    const float* __restrict__ bias,
    const float* __restrict__ g1,
    const float* __restrict__ be1,
    float* __restrict__ dest_param)
{
    constexpr int KTOT = (GEMM == 1) ? CIN : H1;
    constexpr int NS   = KTOT / 64;

    extern __shared__ char smem[];
    __shared__ __half2 s_sc2[H1 / 2];     // BN1 scale (GEMM2 only)
    __shared__ __half2 s_sh2[H1 / 2];     // BN1 shift
    const uint32_t sb = smem_u32(smem);
    const int tid  = threadIdx.x;
    const int lane = tid & 31;
    const int wid  = tid >> 5;
    const int wm   = wid & 1;             // 2 warps along M (32 rows each)
    const int wn   = wid >> 1;            // 4 warps along N (32 cols each)
    const int row0 = blockIdx.x * 64;
    const int col0 = blockIdx.y * 128;

    const __half* A = (GEMM == 1) ? g_A1 : g_yh;
    const __half* B = (GEMM == 1) ? g_W1f : g_W2f;

    if (GEMM == 2) {
        if (tid < H1 / 2) {
            float inv = 1.f / (float)M_TOTAL;
            float m0 = g_sum1[2 * tid] * inv;
            float m1 = g_sum1[2 * tid + 1] * inv;
            float v0 = g_sumsq1[2 * tid] * inv - m0 * m0;
            float v1 = g_sumsq1[2 * tid + 1] * inv - m1 * m1;
            float c0 = g1[2 * tid] * rsqrtf(v0 + BN_EPS);
            float c1 = g1[2 * tid + 1] * rsqrtf(v1 + BN_EPS);
            s_sc2[tid] = __floats2half2_rn(c0, c1);
            s_sh2[tid] = __floats2half2_rn(be1[2 * tid] - m0 * c0,
                                           be1[2 * tid + 1] - m1 * c1);
        }
        // first use is inside the main loop, after CP_WAIT1 + __syncthreads -> ordered
    }

    // ldmatrix row offsets + swizzle keys (128B rows)
    int aoffB[2], asw[2];
#pragma unroll
    for (int mi = 0; mi < 2; mi++) {
        int r = wm * 32 + mi * 16 + (lane & 15);
        aoffB[mi] = r * 128;
        asw[mi]   = r & 7;
    }
    const int asel = lane >> 4;
    int boffB[4], bsw[4];
#pragma unroll
    for (int ni = 0; ni < 4; ni++) {
        int r = wn * 32 + ni * 8 + (lane & 7);
        boffB[ni] = r * 128;
        bsw[ni]   = r & 7;
    }
    const int bsel = (lane >> 3) & 1;

    float acc[2][4][4];
#pragma unroll
    for (int mi = 0; mi < 2; mi++)
#pragma unroll
        for (int ni = 0; ni < 4; ni++)
#pragma unroll
            for (int e = 0; e < 4; e++) acc[mi][ni][e] = 0.f;

    auto issue_stage = [&](int s) {
        const uint32_t bufa = sb + (uint32_t)(s % 3) * GEMM_STAGE;
        const int k0 = s * 64;
        const __half* srcA = A + (size_t)row0 * KTOT + k0;
        const __half* srcB = B + (size_t)col0 * KTOT + k0;
        // A: 64 rows x 8 chunks = 512 chunks (2/thread); B: 128 rows x 8 chunks = 1024 (4/thread)
#pragma unroll
        for (int h = 0; h < 2; h++) {
            int u = tid + 256 * h;
            int r = u >> 3, c = u & 7;
            uint32_t off = r * 128 + ((c ^ (r & 7)) << 4);
            cp16(bufa + off, srcA + (size_t)r * KTOT + c * 8);
        }
#pragma unroll
        for (int h = 0; h < 4; h++) {
            int u = tid + 256 * h;
            int r = u >> 3, c = u & 7;
            uint32_t off = r * 128 + ((c ^ (r & 7)) << 4);
            cp16(bufa + A_STAGE + off, srcB + (size_t)r * KTOT + c * 8);
        }
    };

    auto compute_stage = [&](uint32_t bufa, int s) {
#pragma unroll
        for (int k16 = 0; k16 < 4; k16++) {
            uint32_t a[2][4];
#pragma unroll
            for (int mi = 0; mi < 2; mi++) {
                uint32_t off = aoffB[mi] + ((((k16 * 2 + asel) ^ asw[mi])) << 4);
                ldsm4(a[mi], bufa + off);
            }
            if (GEMM == 2) {
                // BN1 + ReLU on A fragments: regs 0,1 at k = s*64+k16*16+(lane%4)*2; regs 2,3 at k+8
                const int idx2 = s * 32 + k16 * 8 + (lane & 3);
                const __half2 scl = s_sc2[idx2],     shl = s_sh2[idx2];
                const __half2 sch = s_sc2[idx2 + 4], shh = s_sh2[idx2 + 4];
#pragma unroll
                for (int mi = 0; mi < 2; mi++) {
                    __half2* ah = (__half2*)a[mi];
                    ah[0] = __hfma2_relu(ah[0], scl, shl);
                    ah[1] = __hfma2_relu(ah[1], scl, shl);
                    ah[2] = __hfma2_relu(ah[2], sch, shh);
                    ah[3] = __hfma2_relu(ah[3], sch, shh);
                }
            }
            uint32_t bvv[4][2];
#pragma unroll
            for (int ni = 0; ni < 4; ni++) {
                uint32_t off = boffB[ni] + ((((k16 * 2 + bsel) ^ bsw[ni])) << 4);
                ldsm2(bvv[ni], bufa + A_STAGE + off);
            }
#pragma unroll
            for (int mi = 0; mi < 2; mi++)
#pragma unroll
                for (int ni = 0; ni < 4; ni++)
                    mma_f16(acc[mi][ni], a[mi], bvv[ni]);
        }
    };

    issue_stage(0); CP_COMMIT();
    issue_stage(1); CP_COMMIT();

#pragma unroll 1
    for (int s = 0; s < NS; s++) {
        CP_WAIT1();            // stage s landed; stage s+1 in flight
        __syncthreads();       // all warps done with buf (s+2)%3 from iter s-1
        if (s + 2 < NS) issue_stage(s + 2);
        CP_COMMIT();           // uniform group count (empty at tail)
        compute_stage(sb + (uint32_t)(s % 3) * GEMM_STAGE, s);
    }

    // ---------------- epilogue: bias + store + channel stats ----------------
    float* gsum = (GEMM == 1) ? g_sum1 : g_sum2;
    float* gsq  = (GEMM == 1) ? g_sumsq1 : g_sumsq2;
    const int g   = lane >> 2;
    const int tig = lane & 3;
#pragma unroll
    for (int ni = 0; ni < 4; ni++) {
        const int col = col0 + wn * 32 + ni * 8 + tig * 2;
        const float b0v = bias[col], b1v = bias[col + 1];
        float s0 = 0.f, s1 = 0.f, q0 = 0.f, q1 = 0.f;
#pragma unroll
        for (int mi = 0; mi < 2; mi++) {
            const int rA = row0 + wm * 32 + mi * 16 + g;
            float v00 = acc[mi][ni][0] + b0v, v01 = acc[mi][ni][1] + b1v;
            float v10 = acc[mi][ni][2] + b0v, v11 = acc[mi][ni][3] + b1v;
            if (GEMM == 1) {
                *(__half2*)(g_yh + (size_t)rA * H1 + col)       = __floats2half2_rn(v00, v01);
                *(__half2*)(g_yh + (size_t)(rA + 8) * H1 + col) = __floats2half2_rn(v10, v11);
            } else {
                *(float2*)(dest_param + (size_t)rA * H2 + col)       = make_float2(v00, v01);
                *(float2*)(dest_param + (size_t)(rA + 8) * H2 + col) = make_float2(v10, v11);
            }
            s0 += v00 + v10; s1 += v01 + v11;
            q0 += v00 * v00 + v10 * v10; q1 += v01 * v01 + v11 * v11;
        }
#pragma unroll
        for (int m = 4; m <= 16; m <<= 1) {
            s0 += __shfl_xor_sync(0xffffffffu, s0, m);
            s1 += __shfl_xor_sync(0xffffffffu, s1, m);
            q0 += __shfl_xor_sync(0xffffffffu, q0, m);
            q1 += __shfl_xor_sync(0xffffffffu, q1, m);
        }
        if (lane < 4) {
            atomicAdd(&gsum[col], s0);
            atomicAdd(&gsum[col + 1], s1);
            atomicAdd(&gsq[col], q0);
            atomicAdd(&gsq[col + 1], q1);
        }
    }
}

// ================= final: BN2 finalize in-block + apply + ReLU (one float4/thread) =================
__global__ __launch_bounds__(256) void final_bn_kernel(
    const float* __restrict__ g2, const float* __restrict__ be2,
    float* __restrict__ out)
{
    __shared__ float s_sc[H2], s_sh[H2];
    const int tid = threadIdx.x;
    if (tid < H2) {
        float mean = g_sum2[tid] * (1.f / (float)M_TOTAL);
        float var  = g_sumsq2[tid] * (1.f / (float)M_TOTAL) - mean * mean;
        float sc   = g2[tid] * rsqrtf(var + BN_EPS);
        s_sc[tid] = sc;
        s_sh[tid] = be2[tid] - mean * sc;
    }
    __syncthreads();

    const int i = blockIdx.x * 256 + tid;
    float4 v = ((float4*)out)[i];
    int c = (i * 4) & (H2 - 1);
    v.x = fmaxf(fmaf(v.x, s_sc[c + 0], s_sh[c + 0]), 0.f);
    v.y = fmaxf(fmaf(v.y, s_sc[c + 1], s_sh[c + 1]), 0.f);
    v.z = fmaxf(fmaf(v.z, s_sc[c + 2], s_sh[c + 2]), 0.f);
    v.w = fmaxf(fmaf(v.w, s_sc[c + 3], s_sh[c + 3]), 0.f);
    ((float4*)out)[i] = v;
}

// ================= launch =================
extern "C" void kernel_launch(void* const* d_in, const int* in_sizes, int n_in,
                              void* d_out, int out_size)
{
    const float* xyz1  = (const float*)d_in[0];
    const float* xyz2  = (const float*)d_in[1];
    const float* feat1 = (const float*)d_in[2];
    const float* feat2 = (const float*)d_in[3];
    const float* W1    = (const float*)d_in[4];
    const float* b1    = (const float*)d_in[5];
    const float* g1    = (const float*)d_in[6];
    const float* be1   = (const float*)d_in[7];
    const float* W2    = (const float*)d_in[8];
    const float* b2    = (const float*)d_in[9];
    const float* g2    = (const float*)d_in[10];
    const float* be2   = (const float*)d_in[11];
    float* out = (float*)d_out;

    cudaFuncSetAttribute(gemm_mma_kernel<1>, cudaFuncAttributeMaxDynamicSharedMemorySize,
                         GEMM_SMEM);
    cudaFuncSetAttribute(gemm_mma_kernel<2>, cudaFuncAttributeMaxDynamicSharedMemorySize,
                         GEMM_SMEM);

    prep_weights_kernel<<<(H1 * CIN + H2 * H1 + 255) / 256, 256>>>(W1, W2);

    dim3 gknn(NN / QPB, BB);
    knn_interp_kernel<<<gknn, 512>>>(xyz1, xyz2, feat2, feat1);

    gemm_mma_kernel<1><<<dim3(M_TOTAL / 64, H1 / 128), 256, GEMM_SMEM>>>(b1, nullptr, nullptr, nullptr);

    gemm_mma_kernel<2><<<dim3(M_TOTAL / 64, 1), 256, GEMM_SMEM>>>(b2, g1, be1, out);

    final_bn_kernel<<<M_TOTAL * H2 / 4 / 256, 256>>>(g2, be2, out);
}

// round 16
// speedup vs baseline: 1.1846x; 1.1846x over previous
#include <cuda_runtime.h>
#include <cuda_fp16.h>
#include <math.h>
#include <stdint.h>

#define BB 8
#define NN 8192
#define SS 2048
#define C1 128
#define C2 256
#define CIN 384
#define H1 256
#define H2 128
#define M_TOTAL (BB * NN)   /* 65536 */
#define BN_EPS 1e-5f
#define QPB 64              /* queries per KNN block (8 threads each, 512-thread block) */

// ================= scratch (static device globals; no allocation) =================
__device__ __align__(16) __half g_yh[(size_t)M_TOTAL * H1];    // 32 MB GEMM1 out fp16 (pre-BN)
__device__ float g_sum1[H1];
__device__ float g_sumsq1[H1];
__device__ float g_sum2[H2];
__device__ float g_sumsq2[H2];
// activations fp16
__device__ __align__(16) __half g_A1[(size_t)M_TOTAL * CIN];   // 48 MB
// weights fp16 [n][k]
__device__ __align__(16) __half g_W1f[H1 * CIN];
__device__ __align__(16) __half g_W2f[H2 * H1];

// ================= helpers =================
__device__ __forceinline__ uint32_t smem_u32(const void* p) {
    uint32_t a;
    asm("{ .reg .u64 t; cvta.to.shared.u64 t, %1; cvt.u32.u64 %0, t; }" : "=r"(a) : "l"(p));
    return a;
}
__device__ __forceinline__ void ldsm4(uint32_t* r, uint32_t addr) {
    asm volatile("ldmatrix.sync.aligned.m8n8.x4.shared.b16 {%0,%1,%2,%3}, [%4];"
        : "=r"(r[0]), "=r"(r[1]), "=r"(r[2]), "=r"(r[3]) : "r"(addr));
}
__device__ __forceinline__ void ldsm2(uint32_t* r, uint32_t addr) {
    asm volatile("ldmatrix.sync.aligned.m8n8.x2.shared.b16 {%0,%1}, [%2];"
        : "=r"(r[0]), "=r"(r[1]) : "r"(addr));
}
__device__ __forceinline__ void mma_f16(float* c, const uint32_t* a, const uint32_t* b) {
    asm volatile(
        "mma.sync.aligned.m16n8k16.row.col.f32.f16.f16.f32 "
        "{%0,%1,%2,%3}, {%4,%5,%6,%7}, {%8,%9}, {%0,%1,%2,%3};\n"
        : "+f"(c[0]), "+f"(c[1]), "+f"(c[2]), "+f"(c[3])
        : "r"(a[0]), "r"(a[1]), "r"(a[2]), "r"(a[3]), "r"(b[0]), "r"(b[1]));
}
__device__ __forceinline__ void cp16(uint32_t dst, const void* src) {
    asm volatile("cp.async.cg.shared.global [%0], [%1], 16;" :: "r"(dst), "l"(src));
}
#define CP_COMMIT() asm volatile("cp.async.commit_group;" ::: "memory")
#define CP_WAIT1()  asm volatile("cp.async.wait_group 1;" ::: "memory")

// ================= kernel: 3-NN (8 thr/query) + interp + feat1 convert + weight prep =================
__global__ __launch_bounds__(512) void knn_interp_kernel(
    const float* __restrict__ xyz1,
    const float* __restrict__ xyz2,
    const float* __restrict__ feat2,
    const float* __restrict__ feat1,
    const float* __restrict__ W1,
    const float* __restrict__ W2)
{
    __shared__ float4 s_p[SS];          // 32 KB
    __shared__ float  s_w[QPB][3];
    __shared__ int    s_i[QPB][3];

    const int b   = blockIdx.y;
    const int n0  = blockIdx.x * QPB;
    const int tid = threadIdx.x;
    const int qid = tid >> 3;
    const int sub = tid & 7;

    // ---- fused prep: blocks of batch 0 convert weights + zero stats ----
    if (b == 0) {
        const int base = blockIdx.x * 1024;    // 128 blocks x 1024 elems = 131072
        for (int t = tid; t < 1024; t += 512) {
            int i = base + t;
            if (i < H1 * CIN) {
                g_W1f[i] = __float2half_rn(W1[i]);
            } else {
                int j = i - H1 * CIN;
                if (j < H2 * H1) g_W2f[j] = __float2half_rn(W2[j]);
            }
        }
        if (blockIdx.x == 0 && tid < H1) {
            g_sum1[tid] = 0.f; g_sumsq1[tid] = 0.f;
            if (tid < H2) { g_sum2[tid] = 0.f; g_sumsq2[tid] = 0.f; }
        }
    }

    const float* p2 = xyz2 + (size_t)b * SS * 3;
    for (int j = tid; j < SS; j += 512) {
        float x = p2[j * 3 + 0];
        float y = p2[j * 3 + 1];
        float z = p2[j * 3 + 2];
        s_p[j] = make_float4(x, y, z, x * x + y * y + z * z);
    }
    __syncthreads();

    const int   n  = n0 + qid;
    const float* q = xyz1 + ((size_t)b * NN + n) * 3;
    const float qx = q[0], qy = q[1], qz = q[2];
    const float n1 = qx * qx + qy * qy + qz * qz;
    const float mx = -2.f * qx, my = -2.f * qy, mz = -2.f * qz;

    float d0 = 1e30f, d1 = 1e30f, d2v = 1e30f;
    int   i0 = 0, i1 = 0, i2 = 0;

#pragma unroll 8
    for (int jj = 0; jj < SS / 8; jj++) {
        const int j = (jj << 3) | sub;
        float4 c = s_p[j];
        float s = fmaf(mx, c.x, fmaf(my, c.y, fmaf(mz, c.z, c.w)));
        if (s < d2v) {
            if (s < d1) {
                d2v = d1; i2 = i1;
                if (s < d0) { d1 = d0; i1 = i0; d0 = s; i0 = j; }
                else        { d1 = s;  i1 = j; }
            } else {
                d2v = s; i2 = j;
            }
        }
    }

#pragma unroll
    for (int m = 1; m <= 4; m <<= 1) {
        float e0 = __shfl_xor_sync(0xffffffffu, d0, m);
        float e1 = __shfl_xor_sync(0xffffffffu, d1, m);
        float e2 = __shfl_xor_sync(0xffffffffu, d2v, m);
        int   f0 = __shfl_xor_sync(0xffffffffu, i0, m);
        int   f1 = __shfl_xor_sync(0xffffffffu, i1, m);
        int   f2 = __shfl_xor_sync(0xffffffffu, i2, m);
        float es[3] = {e0, e1, e2};
        int   fs[3] = {f0, f1, f2};
#pragma unroll
        for (int t = 0; t < 3; t++) {
            float s = es[t]; int j = fs[t];
            if (s < d2v) {
                if (s < d1) {
                    d2v = d1; i2 = i1;
                    if (s < d0) { d1 = d0; i1 = i0; d0 = s; i0 = j; }
                    else        { d1 = s;  i1 = j; }
                } else {
                    d2v = s; i2 = j;
                }
            }
        }
    }

    if (sub == 0) {
        float da = sqrtf(fmaxf(n1 + d0, 0.f)) + 1e-10f;
        float db = sqrtf(fmaxf(n1 + d1, 0.f)) + 1e-10f;
        float dc = sqrtf(fmaxf(n1 + d2v, 0.f)) + 1e-10f;
        float w0 = 1.f / da, w1 = 1.f / db, w2 = 1.f / dc;
        float inv = 1.f / (w0 + w1 + w2);
        s_w[qid][0] = w0 * inv; s_w[qid][1] = w1 * inv; s_w[qid][2] = w2 * inv;
        s_i[qid][0] = i0; s_i[qid][1] = i1; s_i[qid][2] = i2;
    }
    __syncthreads();

    const int lane = tid & 31;
    const int warp = tid >> 5;
    const float4* f2b = (const float4*)(feat2 + (size_t)b * SS * C2);
    for (int pl = warp; pl < QPB; pl += 16) {
        const float a0 = s_w[pl][0], a1 = s_w[pl][1], a2 = s_w[pl][2];
        const float4* r0 = f2b + (size_t)s_i[pl][0] * (C2 / 4);
        const float4* r1 = f2b + (size_t)s_i[pl][1] * (C2 / 4);
        const float4* r2 = f2b + (size_t)s_i[pl][2] * (C2 / 4);
        const size_t rowo = (size_t)(b * NN + n0 + pl) * CIN;
#pragma unroll
        for (int c = lane; c < C2 / 4; c += 32) {
            float4 va = r0[c], vb = r1[c], vc = r2[c];
            float o0 = a0 * va.x + a1 * vb.x + a2 * vc.x;
            float o1 = a0 * va.y + a1 * vb.y + a2 * vc.y;
            float o2 = a0 * va.z + a1 * vb.z + a2 * vc.z;
            float o3 = a0 * va.w + a1 * vb.w + a2 * vc.w;
            union { uint2 u; __half h[4]; } pk;
            pk.h[0] = __float2half_rn(o0);
            pk.h[1] = __float2half_rn(o1);
            pk.h[2] = __float2half_rn(o2);
            pk.h[3] = __float2half_rn(o3);
            *(uint2*)(g_A1 + rowo + c * 4) = pk.u;
        }
    }

    for (int t = tid; t < QPB * (C1 / 4); t += 512) {
        const int r  = t >> 5;
        const int c4 = (t & 31) * 4;
        const size_t row = (size_t)b * NN + n0 + r;
        float4 v = *(const float4*)(feat1 + row * C1 + c4);
        union { uint2 u; __half h[4]; } pk;
        pk.h[0] = __float2half_rn(v.x);
        pk.h[1] = __float2half_rn(v.y);
        pk.h[2] = __float2half_rn(v.z);
        pk.h[3] = __float2half_rn(v.w);
        *(uint2*)(g_A1 + row * CIN + C2 + c4) = pk.u;
    }
}

// ================= single-product fp16 cp.async MMA GEMM, K64 stages =================
// 3-stage ring, 32KB/stage: A 16KB (128 rows x 128B) | B 16KB.
// Row = 128B = 8 chunks of 16B; chunk c stored at c ^ (r & 7)  (conflict-free ldmatrix).
// GEMM2 fuses BN1+ReLU into A fragments after ldmatrix (raw g_yh in smem).
#define GEMM_STAGE 32768
#define GEMM_SMEM  (3 * GEMM_STAGE)

template<int GEMM>   // 1: A1 x W1 -> g_yh ; 2: relu(bn1(g_yh)) x W2 -> out
__global__ void __launch_bounds__(256, 2) gemm_mma_kernel(
    const float* __restrict__ bias,
    const float* __restrict__ g1,
    const float* __restrict__ be1,
    float* __restrict__ dest_param)
{
    constexpr int KTOT = (GEMM == 1) ? CIN : H1;
    constexpr int NS   = KTOT / 64;

    extern __shared__ char smem[];
    __shared__ __half2 s_sc2[H1 / 2];     // BN1 scale (GEMM2 only)
    __shared__ __half2 s_sh2[H1 / 2];     // BN1 shift
    const uint32_t sb = smem_u32(smem);
    const int tid  = threadIdx.x;
    const int lane = tid & 31;
    const int wid  = tid >> 5;
    const int wm   = wid & 1;
    const int wn   = wid >> 1;
    const int row0 = blockIdx.x * 128;
    const int col0 = blockIdx.y * 128;

    const __half* A = (GEMM == 1) ? g_A1 : g_yh;
    const __half* B = (GEMM == 1) ? g_W1f : g_W2f;

    if (GEMM == 2) {
        if (tid < H1 / 2) {
            float inv = 1.f / (float)M_TOTAL;
            float m0 = g_sum1[2 * tid] * inv;
            float m1 = g_sum1[2 * tid + 1] * inv;
            float v0 = g_sumsq1[2 * tid] * inv - m0 * m0;
            float v1 = g_sumsq1[2 * tid + 1] * inv - m1 * m1;
            float c0 = g1[2 * tid] * rsqrtf(v0 + BN_EPS);
            float c1 = g1[2 * tid + 1] * rsqrtf(v1 + BN_EPS);
            s_sc2[tid] = __floats2half2_rn(c0, c1);
            s_sh2[tid] = __floats2half2_rn(be1[2 * tid] - m0 * c0,
                                           be1[2 * tid + 1] - m1 * c1);
        }
        // first use is inside the main loop, after CP_WAIT1 + __syncthreads -> ordered
    }

    // ldmatrix row offsets + swizzle keys (128B rows)
    int aoffB[4], asw[4];
#pragma unroll
    for (int mi = 0; mi < 4; mi++) {
        int r = wm * 64 + mi * 16 + (lane & 15);
        aoffB[mi] = r * 128;
        asw[mi]   = r & 7;
    }
    const int asel = lane >> 4;
    int boffB[4], bsw[4];
#pragma unroll
    for (int ni = 0; ni < 4; ni++) {
        int r = wn * 32 + ni * 8 + (lane & 7);
        boffB[ni] = r * 128;
        bsw[ni]   = r & 7;
    }
    const int bsel = (lane >> 3) & 1;

    float acc[4][4][4];
#pragma unroll
    for (int mi = 0; mi < 4; mi++)
#pragma unroll
        for (int ni = 0; ni < 4; ni++)
#pragma unroll
            for (int e = 0; e < 4; e++) acc[mi][ni][e] = 0.f;

    auto issue_stage = [&](int s) {
        const uint32_t bufa = sb + (uint32_t)(s % 3) * GEMM_STAGE;
        const int k0 = s * 64;
        const __half* srcA = A + (size_t)row0 * KTOT + k0;
        const __half* srcB = B + (size_t)col0 * KTOT + k0;
        // 1024 chunks per operand (128 rows x 8 chunks), 4 per thread
#pragma unroll
        for (int h = 0; h < 4; h++) {
            int u = tid + 256 * h;
            int r = u >> 3, c = u & 7;
            uint32_t off = r * 128 + ((c ^ (r & 7)) << 4);
            cp16(bufa + off,         srcA + (size_t)r * KTOT + c * 8);
            cp16(bufa + 16384 + off, srcB + (size_t)r * KTOT + c * 8);
        }
    };

    auto compute_stage = [&](uint32_t bufa, int s) {
#pragma unroll
        for (int k16 = 0; k16 < 4; k16++) {
            uint32_t a[4][4];
#pragma unroll
            for (int mi = 0; mi < 4; mi++) {
                uint32_t off = aoffB[mi] + ((((k16 * 2 + asel) ^ asw[mi])) << 4);
                ldsm4(a[mi], bufa + off);
            }
            if (GEMM == 2) {
                // BN1 + ReLU on A fragments: regs 0,1 at k = s*64+k16*16+(lane%4)*2; regs 2,3 at k+8
                const int idx2 = s * 32 + k16 * 8 + (lane & 3);
                const __half2 scl = s_sc2[idx2],     shl = s_sh2[idx2];
                const __half2 sch = s_sc2[idx2 + 4], shh = s_sh2[idx2 + 4];
#pragma unroll
                for (int mi = 0; mi < 4; mi++) {
                    __half2* ah = (__half2*)a[mi];
                    ah[0] = __hfma2_relu(ah[0], scl, shl);
                    ah[1] = __hfma2_relu(ah[1], scl, shl);
                    ah[2] = __hfma2_relu(ah[2], sch, shh);
                    ah[3] = __hfma2_relu(ah[3], sch, shh);
                }
            }
            uint32_t bvv[4][2];
#pragma unroll
            for (int ni = 0; ni < 4; ni++) {
                uint32_t off = boffB[ni] + ((((k16 * 2 + bsel) ^ bsw[ni])) << 4);
                ldsm2(bvv[ni], bufa + 16384 + off);
            }
#pragma unroll
            for (int mi = 0; mi < 4; mi++)
#pragma unroll
                for (int ni = 0; ni < 4; ni++)
                    mma_f16(acc[mi][ni], a[mi], bvv[ni]);
        }
    };

    issue_stage(0); CP_COMMIT();
    issue_stage(1); CP_COMMIT();

#pragma unroll 1
    for (int s = 0; s < NS; s++) {
        CP_WAIT1();            // stage s landed; stage s+1 in flight
        __syncthreads();       // all warps done with buf (s+2)%3 from iter s-1
        if (s + 2 < NS) issue_stage(s + 2);
        CP_COMMIT();           // uniform group count (empty at tail)
        compute_stage(sb + (uint32_t)(s % 3) * GEMM_STAGE, s);
    }

    // ---------------- epilogue: bias + store + channel stats ----------------
    float* gsum = (GEMM == 1) ? g_sum1 : g_sum2;
    float* gsq  = (GEMM == 1) ? g_sumsq1 : g_sumsq2;
    const int g   = lane >> 2;
    const int tig = lane & 3;
#pragma unroll
    for (int ni = 0; ni < 4; ni++) {
        const int col = col0 + wn * 32 + ni * 8 + tig * 2;
        const float b0v = bias[col], b1v = bias[col + 1];
        float s0 = 0.f, s1 = 0.f, q0 = 0.f, q1 = 0.f;
#pragma unroll
        for (int mi = 0; mi < 4; mi++) {
            const int rA = row0 + wm * 64 + mi * 16 + g;
            float v00 = acc[mi][ni][0] + b0v, v01 = acc[mi][ni][1] + b1v;
            float v10 = acc[mi][ni][2] + b0v, v11 = acc[mi][ni][3] + b1v;
            if (GEMM == 1) {
                *(__half2*)(g_yh + (size_t)rA * H1 + col)       = __floats2half2_rn(v00, v01);
                *(__half2*)(g_yh + (size_t)(rA + 8) * H1 + col) = __floats2half2_rn(v10, v11);
            } else {
                *(float2*)(dest_param + (size_t)rA * H2 + col)       = make_float2(v00, v01);
                *(float2*)(dest_param + (size_t)(rA + 8) * H2 + col) = make_float2(v10, v11);
            }
            s0 += v00 + v10; s1 += v01 + v11;
            q0 += v00 * v00 + v10 * v10; q1 += v01 * v01 + v11 * v11;
        }
#pragma unroll
        for (int m = 4; m <= 16; m <<= 1) {
            s0 += __shfl_xor_sync(0xffffffffu, s0, m);
            s1 += __shfl_xor_sync(0xffffffffu, s1, m);
            q0 += __shfl_xor_sync(0xffffffffu, q0, m);
            q1 += __shfl_xor_sync(0xffffffffu, q1, m);
        }
        if (lane < 4) {
            atomicAdd(&gsum[col], s0);
            atomicAdd(&gsum[col + 1], s1);
            atomicAdd(&gsq[col], q0);
            atomicAdd(&gsq[col + 1], q1);
        }
    }
}

// ================= final: BN2 finalize in-block + apply + ReLU (one float4/thread) =================
__global__ __launch_bounds__(256) void final_bn_kernel(
    const float* __restrict__ g2, const float* __restrict__ be2,
    float* __restrict__ out)
{
    __shared__ float s_sc[H2], s_sh[H2];
    const int tid = threadIdx.x;
    if (tid < H2) {
        float mean = g_sum2[tid] * (1.f / (float)M_TOTAL);
        float var  = g_sumsq2[tid] * (1.f / (float)M_TOTAL) - mean * mean;
        float sc   = g2[tid] * rsqrtf(var + BN_EPS);
        s_sc[tid] = sc;
        s_sh[tid] = be2[tid] - mean * sc;
    }
    __syncthreads();

    const int i = blockIdx.x * 256 + tid;
    float4 v = ((float4*)out)[i];
    int c = (i * 4) & (H2 - 1);
    v.x = fmaxf(fmaf(v.x, s_sc[c + 0], s_sh[c + 0]), 0.f);
    v.y = fmaxf(fmaf(v.y, s_sc[c + 1], s_sh[c + 1]), 0.f);
    v.z = fmaxf(fmaf(v.z, s_sc[c + 2], s_sh[c + 2]), 0.f);
    v.w = fmaxf(fmaf(v.w, s_sc[c + 3], s_sh[c + 3]), 0.f);
    ((float4*)out)[i] = v;
}

// ================= launch =================
extern "C" void kernel_launch(void* const* d_in, const int* in_sizes, int n_in,
                              void* d_out, int out_size)
{
    const float* xyz1  = (const float*)d_in[0];
    const float* xyz2  = (const float*)d_in[1];
    const float* feat1 = (const float*)d_in[2];
    const float* feat2 = (const float*)d_in[3];
    const float* W1    = (const float*)d_in[4];
    const float* b1    = (const float*)d_in[5];
    const float* g1    = (const float*)d_in[6];
    const float* be1   = (const float*)d_in[7];
    const float* W2    = (const float*)d_in[8];
    const float* b2    = (const float*)d_in[9];
    const float* g2    = (const float*)d_in[10];
    const float* be2   = (const float*)d_in[11];
    float* out = (float*)d_out;

    cudaFuncSetAttribute(gemm_mma_kernel<1>, cudaFuncAttributeMaxDynamicSharedMemorySize,
                         GEMM_SMEM);
    cudaFuncSetAttribute(gemm_mma_kernel<2>, cudaFuncAttributeMaxDynamicSharedMemorySize,
                         GEMM_SMEM);

    dim3 gknn(NN / QPB, BB);
    knn_interp_kernel<<<gknn, 512>>>(xyz1, xyz2, feat2, feat1, W1, W2);

    gemm_mma_kernel<1><<<dim3(M_TOTAL / 128, H1 / 128), 256, GEMM_SMEM>>>(b1, nullptr, nullptr, nullptr);

    gemm_mma_kernel<2><<<dim3(M_TOTAL / 128, 1), 256, GEMM_SMEM>>>(b2, g1, be1, out);

    final_bn_kernel<<<M_TOTAL * H2 / 4 / 256, 256>>>(g2, be2, out);
}